// round 15
// baseline (speedup 1.0000x reference)
#include <cuda_runtime.h>
#include <cuda_bf16.h>
#include <cstdint>

#define Bn 8
#define Tt 64
#define TWw 62
#define NBT (Bn*Tt)
#define TILE 16384
#define NWIN (Bn*TWw)

// ---------------- device scratch ----------------
__device__ float g_wfT[(size_t)NBT*TILE];      // wf fp32 [bt][d][n]
__device__ float g_P  [NBT*128];
__device__ float g_DIS[NBT*3*128];             // [bt][role][j]
__device__ unsigned short g_wfh[(size_t)NBT*TILE], g_wfl[(size_t)NBT*TILE]; // wf bf16 [n][d]
__device__ unsigned short g_fTh[(size_t)NBT*TILE], g_fTl[(size_t)NBT*TILE]; // featT bf16 [d][n]
__device__ unsigned short g_W1h[TILE], g_W1l[TILE];   // W1T [h][i]
__device__ unsigned short g_W2h[TILE], g_W2l[TILE];   // W2T [o][i]

// ---------------- helpers ----------------
__device__ __forceinline__ uint32_t smem_u32(const void* p){
    uint32_t a;
    asm("{ .reg .u64 t; cvta.to.shared.u64 t, %1; cvt.u32.u64 %0, t; }" : "=r"(a) : "l"(p));
    return a;
}
__device__ __forceinline__ void ldsm4(uint32_t addr, uint32_t r[4]){
    asm volatile("ldmatrix.sync.aligned.m8n8.x4.shared.b16 {%0,%1,%2,%3}, [%4];"
        : "=r"(r[0]), "=r"(r[1]), "=r"(r[2]), "=r"(r[3]) : "r"(addr));
}
__device__ __forceinline__ void mma16816(float* c, const uint32_t a[4], uint32_t b0, uint32_t b1){
    asm volatile("mma.sync.aligned.m16n8k16.row.col.f32.bf16.bf16.f32 "
        "{%0,%1,%2,%3}, {%4,%5,%6,%7}, {%8,%9}, {%0,%1,%2,%3};"
        : "+f"(c[0]), "+f"(c[1]), "+f"(c[2]), "+f"(c[3])
        : "r"(a[0]), "r"(a[1]), "r"(a[2]), "r"(a[3]), "r"(b0), "r"(b1));
}
// fast fp32x2 -> bf16 hi/lo pair
__device__ __forceinline__ void split2(float a, float b, uint32_t& hw, uint32_t& lw){
    uint32_t h;
    asm("cvt.rn.bf16x2.f32 %0, %1, %2;" : "=r"(h) : "f"(b), "f"(a));
    float ah = __uint_as_float(h << 16);
    float bh = __uint_as_float(h & 0xffff0000u);
    uint32_t l;
    asm("cvt.rn.bf16x2.f32 %0, %1, %2;" : "=r"(l) : "f"(b - bh), "f"(a - ah));
    hw = h; lw = l;
}
#define CP_COMMIT() asm volatile("cp.async.commit_group;" ::: "memory")
#define CP_WAIT0()  asm volatile("cp.async.wait_group 0;" ::: "memory")
#define CP_WAIT1()  asm volatile("cp.async.wait_group 1;" ::: "memory")

// ===========================================================================
// Kernel 1 (merged prep): per-bt strips — wf blob, P, wfT fp32, featT blob
// ===========================================================================
#define PADW 133
__global__ __launch_bounds__(256) void prep_kernel(const float* __restrict__ feat,
                                                   const float* __restrict__ w){
    __shared__ float sig[128];
    __shared__ float fs[32][PADW];
    __shared__ float ws[32][PADW];
    __shared__ float pacc[128];
    const int tid = threadIdx.x, warp = tid >> 5, lane = tid & 31;
    const int bt = blockIdx.x;
    if (tid < 128){ sig[tid] = 1.0f / (1.0f + expf(-w[tid])); pacc[tid] = 0.0f; }
    __syncthreads();
    uint32_t* bh = (uint32_t*)g_wfh;
    uint32_t* bl = (uint32_t*)g_wfl;
    uint32_t* fh = (uint32_t*)g_fTh;
    uint32_t* fl = (uint32_t*)g_fTl;

    for (int s = 0; s < 4; s++){
        const int n0 = s*32;
        for (int rr = warp; rr < 32; rr += 8){
            const int row = n0 + rr;
            float4 v = ((const float4*)(feat + (size_t)bt*TILE + (size_t)row*128))[lane];
            fs[rr][lane*4    ] = v.x; fs[rr][lane*4 + 1] = v.y;
            fs[rr][lane*4 + 2] = v.z; fs[rr][lane*4 + 3] = v.w;
            float4 sg = ((const float4*)sig)[lane];
            v.x *= sg.x; v.y *= sg.y; v.z *= sg.z; v.w *= sg.w;
            float sq = v.x*v.x + v.y*v.y + v.z*v.z + v.w*v.w;
#pragma unroll
            for (int off = 16; off; off >>= 1) sq += __shfl_xor_sync(0xffffffffu, sq, off);
            float sc = 1.0f / fmaxf(sqrtf(sq), 1e-12f);
            v.x *= sc; v.y *= sc; v.z *= sc; v.w *= sc;
            ws[rr][lane*4    ] = v.x; ws[rr][lane*4 + 1] = v.y;
            ws[rr][lane*4 + 2] = v.z; ws[rr][lane*4 + 3] = v.w;
            uint32_t h0,l0,h1,l1;
            split2(v.x, v.y, h0, l0);
            split2(v.z, v.w, h1, l1);
            size_t bi = (size_t)bt*8192 + (size_t)row*64 + lane*2;
            bh[bi] = h0;     bl[bi] = l0;
            bh[bi + 1] = h1; bl[bi + 1] = l1;
        }
        __syncthreads();
        if (tid < 128){
            float s0 = 0.0f;
#pragma unroll 8
            for (int r = 0; r < 32; r++) s0 += ws[r][tid];
            pacc[tid] += s0;
        }
        for (int i = tid; i < 2048; i += 256){
            int d = i >> 4, q = i & 15, n = q*2;
            float a = ws[n][d], b = ws[n+1][d];
            *(float2*)(g_wfT + (size_t)bt*TILE + (size_t)d*128 + n0 + n) = make_float2(a, b);
            uint32_t h, l;
            split2(fs[n][d], fs[n+1][d], h, l);
            size_t bi = ((size_t)bt*TILE + (size_t)d*128 + n0 + n) >> 1;
            fh[bi] = h; fl[bi] = l;
        }
        __syncthreads();
    }
    if (tid < 128) g_P[bt*128 + tid] = pacc[tid];
}

// ===========================================================================
// Kernel 2: W1T/W2T blobs (grid = 8)
// ===========================================================================
__global__ __launch_bounds__(256) void prepW_kernel(const float* __restrict__ W1,
                                                    const float* __restrict__ W2){
    __shared__ float ft[128*33];
    const int tid = threadIdx.x, blk = blockIdx.x;
    const int which = blk >> 2, dc = blk & 3;
    const float* S0 = which ? W2 : W1;
    unsigned short* oh = which ? g_W2h : g_W1h;
    unsigned short* ol = which ? g_W2l : g_W1l;
    for (int i = tid; i < 1024; i += 256){
        int r = i >> 3, s = i & 7;
        float4 v = *(const float4*)(S0 + (size_t)r*128 + dc*32 + s*4);
        ft[r*33 + s*4    ] = v.x; ft[r*33 + s*4 + 1] = v.y;
        ft[r*33 + s*4 + 2] = v.z; ft[r*33 + s*4 + 3] = v.w;
    }
    __syncthreads();
    for (int i = tid; i < 2048; i += 256){
        int d = i >> 6, q = i & 63, n0 = q*2;
        uint32_t h, l;
        split2(ft[n0*33 + d], ft[(n0+1)*33 + d], h, l);
        size_t bi = (size_t)(dc*32 + d)*64 + q;
        ((uint32_t*)oh)[bi] = h;
        ((uint32_t*)ol)[bi] = l;
    }
}

// ===========================================================================
// Kernel 3: DIS precompute from fp32 g_wfT
// ===========================================================================
__global__ __launch_bounds__(256) void deg_kernel(){
    __shared__ float P5[5][128];
    __shared__ float red[5][256];
    const int bt = blockIdx.x, b = bt >> 6, t = bt & 63;
    const int tid = threadIdx.x;
    for (int i = tid; i < 640; i += 256){
        int dl = i >> 7, d = i & 127;
        int tt = t + dl - 2;
        P5[dl][d] = (tt >= 0 && tt < 64) ? g_P[(b*64 + tt)*128 + d] : 0.0f;
    }
    __syncthreads();
    const float* wfT = g_wfT + (size_t)bt*TILE;
    const int j = tid & 127, half = tid >> 7;
    float q[5] = {0.f, 0.f, 0.f, 0.f, 0.f};
    for (int d = half*64; d < half*64 + 64; d++){
        float v = wfT[(size_t)d*128 + j];
#pragma unroll
        for (int dl = 0; dl < 5; dl++) q[dl] += v * P5[dl][d];
    }
#pragma unroll
    for (int dl = 0; dl < 5; dl++) red[dl][tid] = q[dl];
    __syncthreads();
    if (tid < 128){
#pragma unroll
        for (int dl = 0; dl < 5; dl++) q[dl] = red[dl][tid] + red[dl][tid + 128];
#pragma unroll
        for (int r = 0; r < 3; r++){
            int tw = t - r;
            if (tw >= 0 && tw <= 61){
                float deg = q[2-r] + q[3-r] + q[4-r];
                g_DIS[(bt*3 + r)*128 + j] = (deg > 0.0f) ? rsqrtf(fmaxf(deg, 1e-38f)) : 0.0f;
            }
        }
    }
}

// ===========================================================================
// Fused: 256 thr, 2 blocks/SM, double-buffered 32-K sub-chunks in SG
// ===========================================================================
#define XH_O   0
#define XL_O   34816
#define SGH_O  69632
#define SGL_O  88064
#define DIS_O  106496
#define B1_O   107008
#define B2_O   107520
#define GM_O   108032
#define BT_O   108544
#define PSS_O  109056
#define PSQ_O  110080
#define FUSED_SMEM 111104

#define LDX 136
#define LDC 72

__device__ __forceinline__ void mma_k16(uint32_t sb,
        uint32_t aH, uint32_t aL, int lda, int ka0,
        uint32_t bH, uint32_t bL, int ldb, int kb0,
        float (*acc)[4], int lane, int wr, int wc){
    const int arow = lane & 15, chalf = (lane >> 4) << 3;
    uint32_t Ah[2][4], Al[2][4];
#pragma unroll
    for (int mi = 0; mi < 2; mi++){
        uint32_t off = (uint32_t)((wr*32 + mi*16 + arow) * lda + ka0 + chalf) * 2;
        ldsm4(sb + aH + off, Ah[mi]);
        ldsm4(sb + aL + off, Al[mi]);
    }
#pragma unroll
    for (int ng = 0; ng < 4; ng++){
        uint32_t off = (uint32_t)((wc*64 + ng*16 + arow) * ldb + kb0 + chalf) * 2;
        uint32_t Bh[4], Bl[4];
        ldsm4(sb + bH + off, Bh);
        ldsm4(sb + bL + off, Bl);
#pragma unroll
        for (int mi = 0; mi < 2; mi++){
            float* c0 = acc[mi*8 + ng*2];
            float* c1 = acc[mi*8 + ng*2 + 1];
            mma16816(c0, Ah[mi], Bh[0], Bh[2]);
            mma16816(c0, Ah[mi], Bl[0], Bl[2]);
            mma16816(c0, Al[mi], Bh[0], Bh[2]);
            mma16816(c1, Ah[mi], Bh[1], Bh[3]);
            mma16816(c1, Ah[mi], Bl[1], Bl[3]);
            mma16816(c1, Al[mi], Bh[1], Bh[3]);
        }
    }
}

// load 32-kcol chunk kc (0..3) of a [128][128] blob pair into SG sub-buffer (0/1)
__device__ __forceinline__ void stage_chunk32(uint32_t sb,
        const unsigned short* __restrict__ sh, const unsigned short* __restrict__ sl,
        int kc, int sub, int tid){
    const char* gh = (const char*)sh + kc*64;
    const char* gl = (const char*)sl + kc*64;
    const uint32_t dsub = (uint32_t)sub*64;
    for (int i = tid; i < 1024; i += 256){
        int half = i >> 9, j = i & 511, r = j >> 2, s = j & 3;
        uint32_t dst = sb + (half ? SGL_O : SGH_O) + (uint32_t)r*144 + dsub + s*16;
        const char* src = (half ? gl : gh) + (size_t)r*256 + s*16;
        asm volatile("cp.async.ca.shared.global [%0], [%1], 16;" :: "r"(dst), "l"(src));
    }
}

// pipelined 128-K stage. ASIDE=1: A = SG chunks, B = X. ASIDE=0: A = X, B = SG.
// caller must have issued chunk0 -> sub0 (+ commit) already.
template<int ASIDE>
__device__ __forceinline__ void run_stage(uint32_t sb,
        const unsigned short* __restrict__ sh, const unsigned short* __restrict__ sl,
        float (*acc)[4], int tid, int lane, int wr, int wc){
#pragma unroll
    for (int c = 0; c < 4; c++){
        if (c < 3){ stage_chunk32(sb, sh, sl, c + 1, (c + 1) & 1, tid); CP_COMMIT(); }
        if (c < 3){ CP_WAIT1(); } else { CP_WAIT0(); }
        __syncthreads();
        const int sub = (c & 1)*32;
        if (ASIDE){
            mma_k16(sb, SGH_O, SGL_O, LDC, sub,      XH_O, XL_O, LDX, c*32,      acc, lane, wr, wc);
            mma_k16(sb, SGH_O, SGL_O, LDC, sub + 16, XH_O, XL_O, LDX, c*32 + 16, acc, lane, wr, wc);
        } else {
            mma_k16(sb, XH_O, XL_O, LDX, c*32,      SGH_O, SGL_O, LDC, sub,      acc, lane, wr, wc);
            mma_k16(sb, XH_O, XL_O, LDX, c*32 + 16, SGH_O, SGL_O, LDC, sub + 16, acc, lane, wr, wc);
        }
        __syncthreads();
    }
}

template<int MODE>
__device__ __forceinline__ void store_acc(uint8_t* smb, float (*acc)[4],
        const float* smf, int xo, int lane, int wr, int wc){
    const int g = lane >> 2, t = lane & 3;
#pragma unroll
    for (int mi = 0; mi < 2; mi++){
        int r0 = wr*32 + mi*16 + g;
#pragma unroll
        for (int ni = 0; ni < 8; ni++){
            int col = wc*64 + ni*8 + t*2;
            float* a = acc[mi*8 + ni];
            float v0 = a[0], v1 = a[1], v2 = a[2], v3 = a[3];
            if (MODE == 1){
                float s0 = smf[xo + r0], s1 = smf[xo + r0 + 8];
                v0 *= s0; v1 *= s0; v2 *= s1; v3 *= s1;
            }
            if (MODE == 2){
                float q0 = smf[xo + col], q1 = smf[xo + col + 1];
                v0 = fmaxf(v0 + q0, 0.0f); v1 = fmaxf(v1 + q1, 0.0f);
                v2 = fmaxf(v2 + q0, 0.0f); v3 = fmaxf(v3 + q1, 0.0f);
            }
            uint32_t h0,l0,h1,l1;
            split2(v0, v1, h0, l0);
            split2(v2, v3, h1, l1);
            uint32_t o0 = (uint32_t)(r0*LDX + col)*2, o1 = (uint32_t)((r0+8)*LDX + col)*2;
            *(uint32_t*)(smb + XH_O + o0) = h0;  *(uint32_t*)(smb + XL_O + o0) = l0;
            *(uint32_t*)(smb + XH_O + o1) = h1;  *(uint32_t*)(smb + XL_O + o1) = l1;
        }
    }
}

__device__ __forceinline__ void zero_acc(float (*acc)[4]){
#pragma unroll
    for (int i = 0; i < 16; i++)
#pragma unroll
        for (int j = 0; j < 4; j++) acc[i][j] = 0.0f;
}

__global__ __launch_bounds__(256, 2)
void fused_kernel(const float* __restrict__ feat,
                  const float* __restrict__ b1, const float* __restrict__ b2,
                  const float* __restrict__ gamma, const float* __restrict__ beta,
                  float* __restrict__ out){
    extern __shared__ uint8_t smb[];
    float* smf = (float*)smb;
    const uint32_t sb = smem_u32(smb);
    const int tid = threadIdx.x, wid = tid >> 5, lane = tid & 31;
    const int wr = wid & 3, wc = wid >> 2;

    const int bw = blockIdx.x;
    const int b = bw / TWw, tw = bw % TWw;
    const size_t bt0 = (size_t)(b*Tt + tw);

    // first chunk of stage C / t2=0 — overlaps all setup
    stage_chunk32(sb, g_fTh + bt0*TILE, g_fTl + bt0*TILE, 0, 0, tid);
    CP_COMMIT();

    if (tid < 128){
        smf[B1_O/4 + tid] = b1[tid];
        smf[B2_O/4 + tid] = b2[tid];
        smf[GM_O/4 + tid] = gamma[tid];
        smf[BT_O/4 + tid] = beta[tid];
        smf[DIS_O/4 + tid] = g_DIS[(bt0 + 2)*384 + 256 + tid];
    }

    float acc[16][4];

    // ---- Stage C: Mt[d2][d1]; A = featT chunks, B = dis-scaled wfT in X
    zero_acc(acc);
    for (int t2 = 0; t2 < 3; t2++){
        const size_t btt = bt0 + t2;
        if (t2){
            stage_chunk32(sb, g_fTh + btt*TILE, g_fTl + btt*TILE, 0, 0, tid);
            CP_COMMIT();
        }
        {   // B = dis-scaled wfT -> X (overlaps chunk0 cp.async)
            const float* wfTp = g_wfT + btt*TILE;
            const float2* disp = (const float2*)(g_DIS + (btt*3 + t2)*128);
            for (int i = tid; i < 8192; i += 256){
                int r = i >> 6, q = i & 63;
                int n0 = q*2;
                float2 v = *(const float2*)(wfTp + (size_t)r*128 + n0);
                float2 dd = disp[q];
                uint32_t h, l;
                split2(v.x*dd.x, v.y*dd.y, h, l);
                uint32_t o = (uint32_t)(r*LDX + n0)*2;
                *(uint32_t*)(smb + XH_O + o) = h;
                *(uint32_t*)(smb + XL_O + o) = l;
            }
        }
        run_stage<1>(sb, g_fTh + btt*TILE, g_fTl + btt*TILE, acc, tid, lane, wr, wc);
    }

    // ---- Stage D: agg[n][d2] = wf2 @ Mt^T
    stage_chunk32(sb, g_wfh + (bt0 + 2)*TILE, g_wfl + (bt0 + 2)*TILE, 0, 0, tid);
    CP_COMMIT();
    store_acc<0>(smb, acc, smf, 0, lane, wr, wc);      // X <- Mt
    zero_acc(acc);
    run_stage<1>(sb, g_wfh + (bt0 + 2)*TILE, g_wfl + (bt0 + 2)*TILE, acc, tid, lane, wr, wc);

    // ---- Stage E: t1 = relu(aggS @ W1 + b1)
    stage_chunk32(sb, g_W1h, g_W1l, 0, 0, tid);
    CP_COMMIT();
    store_acc<1>(smb, acc, smf, DIS_O/4, lane, wr, wc);    // X <- dis2*agg
    zero_acc(acc);
    run_stage<0>(sb, g_W1h, g_W1l, acc, tid, lane, wr, wc);

    // ---- Stage F: t2 = t1 @ W2
    stage_chunk32(sb, g_W2h, g_W2l, 0, 0, tid);
    CP_COMMIT();
    store_acc<2>(smb, acc, smf, B1_O/4, lane, wr, wc);     // X <- t1
    zero_acc(acc);
    run_stage<0>(sb, g_W2h, g_W2l, acc, tid, lane, wr, wc);

    // ---- Epilogue: +b2 +feat, LayerNorm, store
    {
        const int g = lane >> 2, t = lane & 3;
        const float* featLast = feat + (bt0 + 2)*TILE;
#pragma unroll
        for (int mi = 0; mi < 2; mi++){
            int r0 = wr*32 + mi*16 + g;
            float s0 = 0.0f, q0 = 0.0f, s1 = 0.0f, q1 = 0.0f;
#pragma unroll
            for (int ni = 0; ni < 8; ni++){
                int col = wc*64 + ni*8 + t*2;
                float* a = acc[mi*8 + ni];
                float bb0 = smf[B2_O/4 + col], bb1 = smf[B2_O/4 + col + 1];
                float2 f0 = *(const float2*)(featLast + r0*128 + col);
                float2 f1 = *(const float2*)(featLast + (r0+8)*128 + col);
                a[0] += bb0 + f0.x; a[1] += bb1 + f0.y;
                a[2] += bb0 + f1.x; a[3] += bb1 + f1.y;
                s0 += a[0] + a[1];  q0 += a[0]*a[0] + a[1]*a[1];
                s1 += a[2] + a[3];  q1 += a[2]*a[2] + a[3]*a[3];
            }
            s0 += __shfl_xor_sync(0xffffffffu, s0, 1); s0 += __shfl_xor_sync(0xffffffffu, s0, 2);
            q0 += __shfl_xor_sync(0xffffffffu, q0, 1); q0 += __shfl_xor_sync(0xffffffffu, q0, 2);
            s1 += __shfl_xor_sync(0xffffffffu, s1, 1); s1 += __shfl_xor_sync(0xffffffffu, s1, 2);
            q1 += __shfl_xor_sync(0xffffffffu, q1, 1); q1 += __shfl_xor_sync(0xffffffffu, q1, 2);
            if (t == 0){
                smf[PSS_O/4 + r0*2 + wc] = s0;       smf[PSQ_O/4 + r0*2 + wc] = q0;
                smf[PSS_O/4 + (r0+8)*2 + wc] = s1;   smf[PSQ_O/4 + (r0+8)*2 + wc] = q1;
            }
        }
        __syncthreads();
        float* outp = out + (size_t)(b*TWw + tw)*TILE;
#pragma unroll
        for (int mi = 0; mi < 2; mi++){
            int r0 = wr*32 + mi*16 + g;
            float S0 = smf[PSS_O/4 + r0*2] + smf[PSS_O/4 + r0*2 + 1];
            float Q0 = smf[PSQ_O/4 + r0*2] + smf[PSQ_O/4 + r0*2 + 1];
            float S1 = smf[PSS_O/4 + (r0+8)*2] + smf[PSS_O/4 + (r0+8)*2 + 1];
            float Q1 = smf[PSQ_O/4 + (r0+8)*2] + smf[PSQ_O/4 + (r0+8)*2 + 1];
            float mu0 = S0 * 0.0078125f, mu1 = S1 * 0.0078125f;
            float rs0 = rsqrtf(Q0*0.0078125f - mu0*mu0 + 1e-5f);
            float rs1 = rsqrtf(Q1*0.0078125f - mu1*mu1 + 1e-5f);
#pragma unroll
            for (int ni = 0; ni < 8; ni++){
                int col = wc*64 + ni*8 + t*2;
                float* a = acc[mi*8 + ni];
                float gm0 = smf[GM_O/4 + col], gm1 = smf[GM_O/4 + col + 1];
                float bt0v = smf[BT_O/4 + col], bt1v = smf[BT_O/4 + col + 1];
                float2 o0, o1;
                o0.x = (a[0] - mu0)*rs0*gm0 + bt0v;
                o0.y = (a[1] - mu0)*rs0*gm1 + bt1v;
                o1.x = (a[2] - mu1)*rs1*gm0 + bt0v;
                o1.y = (a[3] - mu1)*rs1*gm1 + bt1v;
                *(float2*)(outp + r0*128 + col)     = o0;
                *(float2*)(outp + (r0+8)*128 + col) = o1;
            }
        }
    }
}

// ---------------------------------------------------------------------------
extern "C" void kernel_launch(void* const* d_in, const int* in_sizes, int n_in,
                              void* d_out, int out_size) {
    const float* feat  = (const float*)d_in[0];
    const float* w     = (const float*)d_in[1];
    const float* W1    = (const float*)d_in[2];
    const float* b1    = (const float*)d_in[3];
    const float* W2    = (const float*)d_in[4];
    const float* b2    = (const float*)d_in[5];
    const float* gamma = (const float*)d_in[6];
    const float* beta  = (const float*)d_in[7];
    float* out = (float*)d_out;

    cudaFuncSetAttribute(fused_kernel, cudaFuncAttributeMaxDynamicSharedMemorySize,
                         FUSED_SMEM);

    prep_kernel<<<NBT, 256>>>(feat, w);
    prepW_kernel<<<8, 256>>>(W1, W2);
    deg_kernel<<<NBT, 256>>>();
    fused_kernel<<<NWIN, 256, FUSED_SMEM>>>(feat, b1, b2, gamma, beta, out);
}

// round 16
// speedup vs baseline: 1.0820x; 1.0820x over previous
#include <cuda_runtime.h>
#include <cuda_bf16.h>
#include <cstdint>

#define Bn 8
#define Tt 64
#define TWw 62
#define NBT (Bn*Tt)
#define TILE 16384
#define NWIN (Bn*TWw)

// ---------------- device scratch ----------------
__device__ float g_wfT[(size_t)NBT*TILE];      // wf fp32 [bt][d][n]
__device__ float g_P  [NBT*128];
__device__ float g_DIS[NBT*3*128];             // [bt][role][j]
__device__ unsigned short g_wfh[(size_t)NBT*TILE], g_wfl[(size_t)NBT*TILE]; // wf bf16 [n][d]
__device__ unsigned short g_fTh[(size_t)NBT*TILE], g_fTl[(size_t)NBT*TILE]; // featT bf16 [d][n]
__device__ unsigned short g_W1h[TILE], g_W1l[TILE];   // W1T [h][i]
__device__ unsigned short g_W2h[TILE], g_W2l[TILE];   // W2T [o][i]

// ---------------- helpers ----------------
__device__ __forceinline__ uint32_t smem_u32(const void* p){
    uint32_t a;
    asm("{ .reg .u64 t; cvta.to.shared.u64 t, %1; cvt.u32.u64 %0, t; }" : "=r"(a) : "l"(p));
    return a;
}
__device__ __forceinline__ void ldsm4(uint32_t addr, uint32_t r[4]){
    asm volatile("ldmatrix.sync.aligned.m8n8.x4.shared.b16 {%0,%1,%2,%3}, [%4];"
        : "=r"(r[0]), "=r"(r[1]), "=r"(r[2]), "=r"(r[3]) : "r"(addr));
}
__device__ __forceinline__ void mma16816(float* c, const uint32_t a[4], uint32_t b0, uint32_t b1){
    asm volatile("mma.sync.aligned.m16n8k16.row.col.f32.bf16.bf16.f32 "
        "{%0,%1,%2,%3}, {%4,%5,%6,%7}, {%8,%9}, {%0,%1,%2,%3};"
        : "+f"(c[0]), "+f"(c[1]), "+f"(c[2]), "+f"(c[3])
        : "r"(a[0]), "r"(a[1]), "r"(a[2]), "r"(a[3]), "r"(b0), "r"(b1));
}
// fast fp32x2 -> bf16 hi/lo pair
__device__ __forceinline__ void split2(float a, float b, uint32_t& hw, uint32_t& lw){
    uint32_t h;
    asm("cvt.rn.bf16x2.f32 %0, %1, %2;" : "=r"(h) : "f"(b), "f"(a));
    float ah = __uint_as_float(h << 16);
    float bh = __uint_as_float(h & 0xffff0000u);
    uint32_t l;
    asm("cvt.rn.bf16x2.f32 %0, %1, %2;" : "=r"(l) : "f"(b - bh), "f"(a - ah));
    hw = h; lw = l;
}
#define CP_COMMIT() asm volatile("cp.async.commit_group;" ::: "memory")
#define CP_WAIT0()  asm volatile("cp.async.wait_group 0;" ::: "memory")

// ===========================================================================
// Kernel 1 (merged prep): per-bt strips — wf blob, P, wfT fp32, featT blob
// ===========================================================================
#define PADW 133
__global__ __launch_bounds__(256) void prep_kernel(const float* __restrict__ feat,
                                                   const float* __restrict__ w){
    __shared__ float sig[128];
    __shared__ float fs[32][PADW];
    __shared__ float ws[32][PADW];
    __shared__ float pacc[128];
    const int tid = threadIdx.x, warp = tid >> 5, lane = tid & 31;
    const int bt = blockIdx.x;
    if (tid < 128){ sig[tid] = 1.0f / (1.0f + expf(-w[tid])); pacc[tid] = 0.0f; }
    __syncthreads();
    uint32_t* bh = (uint32_t*)g_wfh;
    uint32_t* bl = (uint32_t*)g_wfl;
    uint32_t* fh = (uint32_t*)g_fTh;
    uint32_t* fl = (uint32_t*)g_fTl;

    for (int s = 0; s < 4; s++){
        const int n0 = s*32;
        for (int rr = warp; rr < 32; rr += 8){
            const int row = n0 + rr;
            float4 v = ((const float4*)(feat + (size_t)bt*TILE + (size_t)row*128))[lane];
            fs[rr][lane*4    ] = v.x; fs[rr][lane*4 + 1] = v.y;
            fs[rr][lane*4 + 2] = v.z; fs[rr][lane*4 + 3] = v.w;
            float4 sg = ((const float4*)sig)[lane];
            v.x *= sg.x; v.y *= sg.y; v.z *= sg.z; v.w *= sg.w;
            float sq = v.x*v.x + v.y*v.y + v.z*v.z + v.w*v.w;
#pragma unroll
            for (int off = 16; off; off >>= 1) sq += __shfl_xor_sync(0xffffffffu, sq, off);
            float sc = 1.0f / fmaxf(sqrtf(sq), 1e-12f);
            v.x *= sc; v.y *= sc; v.z *= sc; v.w *= sc;
            ws[rr][lane*4    ] = v.x; ws[rr][lane*4 + 1] = v.y;
            ws[rr][lane*4 + 2] = v.z; ws[rr][lane*4 + 3] = v.w;
            uint32_t h0,l0,h1,l1;
            split2(v.x, v.y, h0, l0);
            split2(v.z, v.w, h1, l1);
            size_t bi = (size_t)bt*8192 + (size_t)row*64 + lane*2;
            bh[bi] = h0;     bl[bi] = l0;
            bh[bi + 1] = h1; bl[bi + 1] = l1;
        }
        __syncthreads();
        if (tid < 128){
            float s0 = 0.0f;
#pragma unroll 8
            for (int r = 0; r < 32; r++) s0 += ws[r][tid];
            pacc[tid] += s0;
        }
        for (int i = tid; i < 2048; i += 256){
            int d = i >> 4, q = i & 15, n = q*2;
            float a = ws[n][d], b = ws[n+1][d];
            *(float2*)(g_wfT + (size_t)bt*TILE + (size_t)d*128 + n0 + n) = make_float2(a, b);
            uint32_t h, l;
            split2(fs[n][d], fs[n+1][d], h, l);
            size_t bi = ((size_t)bt*TILE + (size_t)d*128 + n0 + n) >> 1;
            fh[bi] = h; fl[bi] = l;
        }
        __syncthreads();
    }
    if (tid < 128) g_P[bt*128 + tid] = pacc[tid];
}

// ===========================================================================
// Kernel 2: deg (blocks 0..NBT-1) + W blobs (blocks NBT..NBT+7)
// ===========================================================================
__global__ __launch_bounds__(256) void deg_kernel(const float* __restrict__ W1,
                                                  const float* __restrict__ W2){
    __shared__ float P5[5][128];
    __shared__ float red[5][256];
    const int tid = threadIdx.x;
    if (blockIdx.x >= NBT){
        // ---- W-blob branch (uses P5/red space as a transpose buffer)
        float* ft = (float*)P5;    // need 128*33 floats <= shared? 5*128+5*256=1920 floats: too small
        // use a dedicated static buffer instead:
        __shared__ float wtb[128*33];
        const int k = blockIdx.x - NBT;
        const int which = k >> 2, dc = k & 3;
        const float* S0 = which ? W2 : W1;
        unsigned short* oh = which ? g_W2h : g_W1h;
        unsigned short* ol = which ? g_W2l : g_W1l;
        for (int i = tid; i < 1024; i += 256){
            int r = i >> 3, s = i & 7;
            float4 v = *(const float4*)(S0 + (size_t)r*128 + dc*32 + s*4);
            wtb[r*33 + s*4    ] = v.x; wtb[r*33 + s*4 + 1] = v.y;
            wtb[r*33 + s*4 + 2] = v.z; wtb[r*33 + s*4 + 3] = v.w;
        }
        __syncthreads();
        for (int i = tid; i < 2048; i += 256){
            int d = i >> 6, q = i & 63, n0 = q*2;
            uint32_t h, l;
            split2(wtb[n0*33 + d], wtb[(n0+1)*33 + d], h, l);
            size_t bi = (size_t)(dc*32 + d)*64 + q;
            ((uint32_t*)oh)[bi] = h;
            ((uint32_t*)ol)[bi] = l;
        }
        (void)ft;
        return;
    }
    const int bt = blockIdx.x, b = bt >> 6, t = bt & 63;
    for (int i = tid; i < 640; i += 256){
        int dl = i >> 7, d = i & 127;
        int tt = t + dl - 2;
        P5[dl][d] = (tt >= 0 && tt < 64) ? g_P[(b*64 + tt)*128 + d] : 0.0f;
    }
    __syncthreads();
    const float* wfT = g_wfT + (size_t)bt*TILE;
    const int j = tid & 127, half = tid >> 7;
    float q[5] = {0.f, 0.f, 0.f, 0.f, 0.f};
    for (int d = half*64; d < half*64 + 64; d++){
        float v = wfT[(size_t)d*128 + j];
#pragma unroll
        for (int dl = 0; dl < 5; dl++) q[dl] += v * P5[dl][d];
    }
#pragma unroll
    for (int dl = 0; dl < 5; dl++) red[dl][tid] = q[dl];
    __syncthreads();
    if (tid < 128){
#pragma unroll
        for (int dl = 0; dl < 5; dl++) q[dl] = red[dl][tid] + red[dl][tid + 128];
#pragma unroll
        for (int r = 0; r < 3; r++){
            int tw = t - r;
            if (tw >= 0 && tw <= 61){
                float deg = q[2-r] + q[3-r] + q[4-r];
                g_DIS[(bt*3 + r)*128 + j] = (deg > 0.0f) ? rsqrtf(fmaxf(deg, 1e-38f)) : 0.0f;
            }
        }
    }
}

// ===========================================================================
// Fused (R14, best known): 256 thr, 2 blocks/SM, one window per block
// ===========================================================================
#define XH_O   0
#define XL_O   34816
#define SGH_O  69632
#define SGL_O  88064
#define DIS_O  106496
#define B1_O   107008
#define B2_O   107520
#define GM_O   108032
#define BT_O   108544
#define PSS_O  109056
#define PSQ_O  110080
#define FUSED_SMEM 111104

#define LDX 136
#define LDC 72

__device__ __forceinline__ void mma_k16(uint32_t sb,
        uint32_t aH, uint32_t aL, int lda, int ka0,
        uint32_t bH, uint32_t bL, int ldb, int kb0,
        float (*acc)[4], int lane, int wr, int wc){
    const int arow = lane & 15, chalf = (lane >> 4) << 3;
    uint32_t Ah[2][4], Al[2][4];
#pragma unroll
    for (int mi = 0; mi < 2; mi++){
        uint32_t off = (uint32_t)((wr*32 + mi*16 + arow) * lda + ka0 + chalf) * 2;
        ldsm4(sb + aH + off, Ah[mi]);
        ldsm4(sb + aL + off, Al[mi]);
    }
#pragma unroll
    for (int ng = 0; ng < 4; ng++){
        uint32_t off = (uint32_t)((wc*64 + ng*16 + arow) * ldb + kb0 + chalf) * 2;
        uint32_t Bh[4], Bl[4];
        ldsm4(sb + bH + off, Bh);
        ldsm4(sb + bL + off, Bl);
#pragma unroll
        for (int mi = 0; mi < 2; mi++){
            float* c0 = acc[mi*8 + ng*2];
            float* c1 = acc[mi*8 + ng*2 + 1];
            mma16816(c0, Ah[mi], Bh[0], Bh[2]);
            mma16816(c0, Ah[mi], Bl[0], Bl[2]);
            mma16816(c0, Al[mi], Bh[0], Bh[2]);
            mma16816(c1, Ah[mi], Bh[1], Bh[3]);
            mma16816(c1, Ah[mi], Bl[1], Bl[3]);
            mma16816(c1, Al[mi], Bh[1], Bh[3]);
        }
    }
}

__device__ __forceinline__ void stage_chunk(uint32_t sb,
        const unsigned short* __restrict__ sh, const unsigned short* __restrict__ sl,
        int kc, int tid){
    const char* gh = (const char*)sh + kc*128;
    const char* gl = (const char*)sl + kc*128;
    for (int i = tid; i < 2048; i += 256){
        int half = i >> 10, j = i & 1023, r = j >> 3, s = j & 7;
        uint32_t dst = sb + (half ? SGL_O : SGH_O) + (uint32_t)r*(LDC*2) + s*16;
        const char* src = (half ? gl : gh) + (size_t)r*256 + s*16;
        asm volatile("cp.async.ca.shared.global [%0], [%1], 16;" :: "r"(dst), "l"(src));
    }
}

template<int MODE>
__device__ __forceinline__ void store_acc(uint8_t* smb, float (*acc)[4],
        const float* smf, int xo, int lane, int wr, int wc){
    const int g = lane >> 2, t = lane & 3;
#pragma unroll
    for (int mi = 0; mi < 2; mi++){
        int r0 = wr*32 + mi*16 + g;
#pragma unroll
        for (int ni = 0; ni < 8; ni++){
            int col = wc*64 + ni*8 + t*2;
            float* a = acc[mi*8 + ni];
            float v0 = a[0], v1 = a[1], v2 = a[2], v3 = a[3];
            if (MODE == 1){
                float s0 = smf[xo + r0], s1 = smf[xo + r0 + 8];
                v0 *= s0; v1 *= s0; v2 *= s1; v3 *= s1;
            }
            if (MODE == 2){
                float q0 = smf[xo + col], q1 = smf[xo + col + 1];
                v0 = fmaxf(v0 + q0, 0.0f); v1 = fmaxf(v1 + q1, 0.0f);
                v2 = fmaxf(v2 + q0, 0.0f); v3 = fmaxf(v3 + q1, 0.0f);
            }
            uint32_t h0,l0,h1,l1;
            split2(v0, v1, h0, l0);
            split2(v2, v3, h1, l1);
            uint32_t o0 = (uint32_t)(r0*LDX + col)*2, o1 = (uint32_t)((r0+8)*LDX + col)*2;
            *(uint32_t*)(smb + XH_O + o0) = h0;  *(uint32_t*)(smb + XL_O + o0) = l0;
            *(uint32_t*)(smb + XH_O + o1) = h1;  *(uint32_t*)(smb + XL_O + o1) = l1;
        }
    }
}

__device__ __forceinline__ void zero_acc(float (*acc)[4]){
#pragma unroll
    for (int i = 0; i < 16; i++)
#pragma unroll
        for (int j = 0; j < 4; j++) acc[i][j] = 0.0f;
}

__global__ __launch_bounds__(256, 2)
void fused_kernel(const float* __restrict__ feat,
                  const float* __restrict__ b1, const float* __restrict__ b2,
                  const float* __restrict__ gamma, const float* __restrict__ beta,
                  float* __restrict__ out){
    extern __shared__ uint8_t smb[];
    float* smf = (float*)smb;
    const uint32_t sb = smem_u32(smb);
    const int tid = threadIdx.x, wid = tid >> 5, lane = tid & 31;
    const int wr = wid & 3, wc = wid >> 2;

    const int bw = blockIdx.x;
    const int b = bw / TWw, tw = bw % TWw;
    const size_t bt0 = (size_t)(b*Tt + tw);

    stage_chunk(sb, g_fTh + bt0*TILE, g_fTl + bt0*TILE, 0, tid);
    CP_COMMIT();

    if (tid < 128){
        smf[B1_O/4 + tid] = b1[tid];
        smf[B2_O/4 + tid] = b2[tid];
        smf[GM_O/4 + tid] = gamma[tid];
        smf[BT_O/4 + tid] = beta[tid];
        smf[DIS_O/4 + tid] = g_DIS[(bt0 + 2)*384 + 256 + tid];
    }

    float acc[16][4];

    // ---- Stage C
    zero_acc(acc);
    for (int t2 = 0; t2 < 3; t2++){
        const size_t btt = bt0 + t2;
        if (t2){
            stage_chunk(sb, g_fTh + btt*TILE, g_fTl + btt*TILE, 0, tid);
            CP_COMMIT();
        }
        {
            const float* wfTp = g_wfT + btt*TILE;
            const float2* disp = (const float2*)(g_DIS + (btt*3 + t2)*128);
            for (int i = tid; i < 8192; i += 256){
                int r = i >> 6, q = i & 63;
                int n0 = q*2;
                float2 v = *(const float2*)(wfTp + (size_t)r*128 + n0);
                float2 dd = disp[q];
                uint32_t h, l;
                split2(v.x*dd.x, v.y*dd.y, h, l);
                uint32_t o = (uint32_t)(r*LDX + n0)*2;
                *(uint32_t*)(smb + XH_O + o) = h;
                *(uint32_t*)(smb + XL_O + o) = l;
            }
        }
        CP_WAIT0();
        __syncthreads();
#pragma unroll
        for (int k = 0; k < 4; k++)
            mma_k16(sb, SGH_O, SGL_O, LDC, k*16, XH_O, XL_O, LDX, k*16, acc, lane, wr, wc);
        __syncthreads();
        stage_chunk(sb, g_fTh + btt*TILE, g_fTl + btt*TILE, 1, tid);
        CP_COMMIT(); CP_WAIT0();
        __syncthreads();
#pragma unroll
        for (int k = 0; k < 4; k++)
            mma_k16(sb, SGH_O, SGL_O, LDC, k*16, XH_O, XL_O, LDX, 64 + k*16, acc, lane, wr, wc);
        __syncthreads();
    }

    // ---- Stage D
    stage_chunk(sb, g_wfh + (bt0 + 2)*TILE, g_wfl + (bt0 + 2)*TILE, 0, tid);
    CP_COMMIT();
    store_acc<0>(smb, acc, smf, 0, lane, wr, wc);
    zero_acc(acc);
    CP_WAIT0();
    __syncthreads();
#pragma unroll
    for (int k = 0; k < 4; k++)
        mma_k16(sb, SGH_O, SGL_O, LDC, k*16, XH_O, XL_O, LDX, k*16, acc, lane, wr, wc);
    __syncthreads();
    stage_chunk(sb, g_wfh + (bt0 + 2)*TILE, g_wfl + (bt0 + 2)*TILE, 1, tid);
    CP_COMMIT(); CP_WAIT0();
    __syncthreads();
#pragma unroll
    for (int k = 0; k < 4; k++)
        mma_k16(sb, SGH_O, SGL_O, LDC, k*16, XH_O, XL_O, LDX, 64 + k*16, acc, lane, wr, wc);
    __syncthreads();

    // ---- Stage E
    stage_chunk(sb, g_W1h, g_W1l, 0, tid);
    CP_COMMIT();
    store_acc<1>(smb, acc, smf, DIS_O/4, lane, wr, wc);
    zero_acc(acc);
    CP_WAIT0();
    __syncthreads();
#pragma unroll
    for (int k = 0; k < 4; k++)
        mma_k16(sb, XH_O, XL_O, LDX, k*16, SGH_O, SGL_O, LDC, k*16, acc, lane, wr, wc);
    __syncthreads();
    stage_chunk(sb, g_W1h, g_W1l, 1, tid);
    CP_COMMIT(); CP_WAIT0();
    __syncthreads();
#pragma unroll
    for (int k = 0; k < 4; k++)
        mma_k16(sb, XH_O, XL_O, LDX, 64 + k*16, SGH_O, SGL_O, LDC, k*16, acc, lane, wr, wc);
    __syncthreads();

    // ---- Stage F
    stage_chunk(sb, g_W2h, g_W2l, 0, tid);
    CP_COMMIT();
    store_acc<2>(smb, acc, smf, B1_O/4, lane, wr, wc);
    zero_acc(acc);
    CP_WAIT0();
    __syncthreads();
#pragma unroll
    for (int k = 0; k < 4; k++)
        mma_k16(sb, XH_O, XL_O, LDX, k*16, SGH_O, SGL_O, LDC, k*16, acc, lane, wr, wc);
    __syncthreads();
    stage_chunk(sb, g_W2h, g_W2l, 1, tid);
    CP_COMMIT(); CP_WAIT0();
    __syncthreads();
#pragma unroll
    for (int k = 0; k < 4; k++)
        mma_k16(sb, XH_O, XL_O, LDX, 64 + k*16, SGH_O, SGL_O, LDC, k*16, acc, lane, wr, wc);

    // ---- Epilogue
    {
        const int g = lane >> 2, t = lane & 3;
        const float* featLast = feat + (bt0 + 2)*TILE;
#pragma unroll
        for (int mi = 0; mi < 2; mi++){
            int r0 = wr*32 + mi*16 + g;
            float s0 = 0.0f, q0 = 0.0f, s1 = 0.0f, q1 = 0.0f;
#pragma unroll
            for (int ni = 0; ni < 8; ni++){
                int col = wc*64 + ni*8 + t*2;
                float* a = acc[mi*8 + ni];
                float bb0 = smf[B2_O/4 + col], bb1 = smf[B2_O/4 + col + 1];
                float2 f0 = *(const float2*)(featLast + r0*128 + col);
                float2 f1 = *(const float2*)(featLast + (r0+8)*128 + col);
                a[0] += bb0 + f0.x; a[1] += bb1 + f0.y;
                a[2] += bb0 + f1.x; a[3] += bb1 + f1.y;
                s0 += a[0] + a[1];  q0 += a[0]*a[0] + a[1]*a[1];
                s1 += a[2] + a[3];  q1 += a[2]*a[2] + a[3]*a[3];
            }
            s0 += __shfl_xor_sync(0xffffffffu, s0, 1); s0 += __shfl_xor_sync(0xffffffffu, s0, 2);
            q0 += __shfl_xor_sync(0xffffffffu, q0, 1); q0 += __shfl_xor_sync(0xffffffffu, q0, 2);
            s1 += __shfl_xor_sync(0xffffffffu, s1, 1); s1 += __shfl_xor_sync(0xffffffffu, s1, 2);
            q1 += __shfl_xor_sync(0xffffffffu, q1, 1); q1 += __shfl_xor_sync(0xffffffffu, q1, 2);
            if (t == 0){
                smf[PSS_O/4 + r0*2 + wc] = s0;       smf[PSQ_O/4 + r0*2 + wc] = q0;
                smf[PSS_O/4 + (r0+8)*2 + wc] = s1;   smf[PSQ_O/4 + (r0+8)*2 + wc] = q1;
            }
        }
        __syncthreads();
        float* outp = out + (size_t)(b*TWw + tw)*TILE;
#pragma unroll
        for (int mi = 0; mi < 2; mi++){
            int r0 = wr*32 + mi*16 + g;
            float S0 = smf[PSS_O/4 + r0*2] + smf[PSS_O/4 + r0*2 + 1];
            float Q0 = smf[PSQ_O/4 + r0*2] + smf[PSQ_O/4 + r0*2 + 1];
            float S1 = smf[PSS_O/4 + (r0+8)*2] + smf[PSS_O/4 + (r0+8)*2 + 1];
            float Q1 = smf[PSQ_O/4 + (r0+8)*2] + smf[PSQ_O/4 + (r0+8)*2 + 1];
            float mu0 = S0 * 0.0078125f, mu1 = S1 * 0.0078125f;
            float rs0 = rsqrtf(Q0*0.0078125f - mu0*mu0 + 1e-5f);
            float rs1 = rsqrtf(Q1*0.0078125f - mu1*mu1 + 1e-5f);
#pragma unroll
            for (int ni = 0; ni < 8; ni++){
                int col = wc*64 + ni*8 + t*2;
                float* a = acc[mi*8 + ni];
                float gm0 = smf[GM_O/4 + col], gm1 = smf[GM_O/4 + col + 1];
                float bt0v = smf[BT_O/4 + col], bt1v = smf[BT_O/4 + col + 1];
                float2 o0, o1;
                o0.x = (a[0] - mu0)*rs0*gm0 + bt0v;
                o0.y = (a[1] - mu0)*rs0*gm1 + bt1v;
                o1.x = (a[2] - mu1)*rs1*gm0 + bt0v;
                o1.y = (a[3] - mu1)*rs1*gm1 + bt1v;
                *(float2*)(outp + r0*128 + col)     = o0;
                *(float2*)(outp + (r0+8)*128 + col) = o1;
            }
        }
    }
}

// ---------------------------------------------------------------------------
extern "C" void kernel_launch(void* const* d_in, const int* in_sizes, int n_in,
                              void* d_out, int out_size) {
    const float* feat  = (const float*)d_in[0];
    const float* w     = (const float*)d_in[1];
    const float* W1    = (const float*)d_in[2];
    const float* b1    = (const float*)d_in[3];
    const float* W2    = (const float*)d_in[4];
    const float* b2    = (const float*)d_in[5];
    const float* gamma = (const float*)d_in[6];
    const float* beta  = (const float*)d_in[7];
    float* out = (float*)d_out;

    cudaFuncSetAttribute(fused_kernel, cudaFuncAttributeMaxDynamicSharedMemorySize,
                         FUSED_SMEM);

    prep_kernel<<<NBT, 256>>>(feat, w);
    deg_kernel<<<NBT + 8, 256>>>(W1, W2);
    fused_kernel<<<NWIN, 256, FUSED_SMEM>>>(feat, b1, b2, gamma, beta, out);
}

// round 17
// speedup vs baseline: 1.1271x; 1.0416x over previous
#include <cuda_runtime.h>
#include <cuda_bf16.h>
#include <cstdint>

#define Bn 8
#define Tt 64
#define TWw 62
#define NBT (Bn*Tt)
#define TILE 16384
#define NWIN (Bn*TWw)

// ---------------- device scratch ----------------
__device__ float g_wfT[(size_t)NBT*TILE];      // wf fp32 [bt][d][n]
__device__ float g_P  [NBT*128];
__device__ float g_DIS[NBT*3*128];             // [bt][role][j]
__device__ unsigned short g_wfh[(size_t)NBT*TILE], g_wfl[(size_t)NBT*TILE]; // wf bf16 [n][d]
__device__ unsigned short g_fTh[(size_t)NBT*TILE], g_fTl[(size_t)NBT*TILE]; // featT bf16 [d][n]
__device__ unsigned short g_W1h[TILE], g_W1l[TILE];   // W1T [h][i]
__device__ unsigned short g_W2h[TILE], g_W2l[TILE];   // W2T [o][i]

// ---------------- helpers ----------------
__device__ __forceinline__ uint32_t smem_u32(const void* p){
    uint32_t a;
    asm("{ .reg .u64 t; cvta.to.shared.u64 t, %1; cvt.u32.u64 %0, t; }" : "=r"(a) : "l"(p));
    return a;
}
__device__ __forceinline__ void ldsm4(uint32_t addr, uint32_t r[4]){
    asm volatile("ldmatrix.sync.aligned.m8n8.x4.shared.b16 {%0,%1,%2,%3}, [%4];"
        : "=r"(r[0]), "=r"(r[1]), "=r"(r[2]), "=r"(r[3]) : "r"(addr));
}
__device__ __forceinline__ void mma16816(float* c, const uint32_t a[4], uint32_t b0, uint32_t b1){
    asm volatile("mma.sync.aligned.m16n8k16.row.col.f32.bf16.bf16.f32 "
        "{%0,%1,%2,%3}, {%4,%5,%6,%7}, {%8,%9}, {%0,%1,%2,%3};"
        : "+f"(c[0]), "+f"(c[1]), "+f"(c[2]), "+f"(c[3])
        : "r"(a[0]), "r"(a[1]), "r"(a[2]), "r"(a[3]), "r"(b0), "r"(b1));
}
// fast fp32x2 -> bf16 hi/lo pair
__device__ __forceinline__ void split2(float a, float b, uint32_t& hw, uint32_t& lw){
    uint32_t h;
    asm("cvt.rn.bf16x2.f32 %0, %1, %2;" : "=r"(h) : "f"(b), "f"(a));
    float ah = __uint_as_float(h << 16);
    float bh = __uint_as_float(h & 0xffff0000u);
    uint32_t l;
    asm("cvt.rn.bf16x2.f32 %0, %1, %2;" : "=r"(l) : "f"(b - bh), "f"(a - ah));
    hw = h; lw = l;
}
#define CP_COMMIT() asm volatile("cp.async.commit_group;" ::: "memory")
#define CP_WAIT0()  asm volatile("cp.async.wait_group 0;" ::: "memory")

// ===========================================================================
// Kernel 1 (merged prep): per-bt strips — wf blob, P, wfT fp32, featT blob
// ===========================================================================
#define PADW 133
__global__ __launch_bounds__(256) void prep_kernel(const float* __restrict__ feat,
                                                   const float* __restrict__ w){
    __shared__ float sig[128];
    __shared__ float fs[32][PADW];
    __shared__ float ws[32][PADW];
    __shared__ float pacc[128];
    const int tid = threadIdx.x, warp = tid >> 5, lane = tid & 31;
    const int bt = blockIdx.x;
    if (tid < 128){ sig[tid] = 1.0f / (1.0f + expf(-w[tid])); pacc[tid] = 0.0f; }
    __syncthreads();
    uint32_t* bh = (uint32_t*)g_wfh;
    uint32_t* bl = (uint32_t*)g_wfl;
    uint32_t* fh = (uint32_t*)g_fTh;
    uint32_t* fl = (uint32_t*)g_fTl;

    for (int s = 0; s < 4; s++){
        const int n0 = s*32;
        for (int rr = warp; rr < 32; rr += 8){
            const int row = n0 + rr;
            float4 v = ((const float4*)(feat + (size_t)bt*TILE + (size_t)row*128))[lane];
            fs[rr][lane*4    ] = v.x; fs[rr][lane*4 + 1] = v.y;
            fs[rr][lane*4 + 2] = v.z; fs[rr][lane*4 + 3] = v.w;
            float4 sg = ((const float4*)sig)[lane];
            v.x *= sg.x; v.y *= sg.y; v.z *= sg.z; v.w *= sg.w;
            float sq = v.x*v.x + v.y*v.y + v.z*v.z + v.w*v.w;
#pragma unroll
            for (int off = 16; off; off >>= 1) sq += __shfl_xor_sync(0xffffffffu, sq, off);
            float sc = 1.0f / fmaxf(sqrtf(sq), 1e-12f);
            v.x *= sc; v.y *= sc; v.z *= sc; v.w *= sc;
            ws[rr][lane*4    ] = v.x; ws[rr][lane*4 + 1] = v.y;
            ws[rr][lane*4 + 2] = v.z; ws[rr][lane*4 + 3] = v.w;
            uint32_t h0,l0,h1,l1;
            split2(v.x, v.y, h0, l0);
            split2(v.z, v.w, h1, l1);
            size_t bi = (size_t)bt*8192 + (size_t)row*64 + lane*2;
            bh[bi] = h0;     bl[bi] = l0;
            bh[bi + 1] = h1; bl[bi + 1] = l1;
        }
        __syncthreads();
        if (tid < 128){
            float s0 = 0.0f;
#pragma unroll 8
            for (int r = 0; r < 32; r++) s0 += ws[r][tid];
            pacc[tid] += s0;
        }
        for (int i = tid; i < 2048; i += 256){
            int d = i >> 4, q = i & 15, n = q*2;
            float a = ws[n][d], b = ws[n+1][d];
            *(float2*)(g_wfT + (size_t)bt*TILE + (size_t)d*128 + n0 + n) = make_float2(a, b);
            uint32_t h, l;
            split2(fs[n][d], fs[n+1][d], h, l);
            size_t bi = ((size_t)bt*TILE + (size_t)d*128 + n0 + n) >> 1;
            fh[bi] = h; fl[bi] = l;
        }
        __syncthreads();
    }
    if (tid < 128) g_P[bt*128 + tid] = pacc[tid];
}

// ===========================================================================
// Kernel 2: deg (blocks 0..NBT-1) + W blobs (blocks NBT..NBT+7)
// ===========================================================================
__global__ __launch_bounds__(256) void deg_kernel(const float* __restrict__ W1,
                                                  const float* __restrict__ W2){
    __shared__ float P5[5][128];
    __shared__ float red[5][256];
    const int tid = threadIdx.x;
    if (blockIdx.x >= NBT){
        __shared__ float wtb[128*33];
        const int k = blockIdx.x - NBT;
        const int which = k >> 2, dc = k & 3;
        const float* S0 = which ? W2 : W1;
        unsigned short* oh = which ? g_W2h : g_W1h;
        unsigned short* ol = which ? g_W2l : g_W1l;
        for (int i = tid; i < 1024; i += 256){
            int r = i >> 3, s = i & 7;
            float4 v = *(const float4*)(S0 + (size_t)r*128 + dc*32 + s*4);
            wtb[r*33 + s*4    ] = v.x; wtb[r*33 + s*4 + 1] = v.y;
            wtb[r*33 + s*4 + 2] = v.z; wtb[r*33 + s*4 + 3] = v.w;
        }
        __syncthreads();
        for (int i = tid; i < 2048; i += 256){
            int d = i >> 6, q = i & 63, n0 = q*2;
            uint32_t h, l;
            split2(wtb[n0*33 + d], wtb[(n0+1)*33 + d], h, l);
            size_t bi = (size_t)(dc*32 + d)*64 + q;
            ((uint32_t*)oh)[bi] = h;
            ((uint32_t*)ol)[bi] = l;
        }
        return;
    }
    const int bt = blockIdx.x, b = bt >> 6, t = bt & 63;
    for (int i = tid; i < 640; i += 256){
        int dl = i >> 7, d = i & 127;
        int tt = t + dl - 2;
        P5[dl][d] = (tt >= 0 && tt < 64) ? g_P[(b*64 + tt)*128 + d] : 0.0f;
    }
    __syncthreads();
    const float* wfT = g_wfT + (size_t)bt*TILE;
    const int j = tid & 127, half = tid >> 7;
    float q[5] = {0.f, 0.f, 0.f, 0.f, 0.f};
    for (int d = half*64; d < half*64 + 64; d++){
        float v = wfT[(size_t)d*128 + j];
#pragma unroll
        for (int dl = 0; dl < 5; dl++) q[dl] += v * P5[dl][d];
    }
#pragma unroll
    for (int dl = 0; dl < 5; dl++) red[dl][tid] = q[dl];
    __syncthreads();
    if (tid < 128){
#pragma unroll
        for (int dl = 0; dl < 5; dl++) q[dl] = red[dl][tid] + red[dl][tid + 128];
#pragma unroll
        for (int r = 0; r < 3; r++){
            int tw = t - r;
            if (tw >= 0 && tw <= 61){
                float deg = q[2-r] + q[3-r] + q[4-r];
                g_DIS[(bt*3 + r)*128 + j] = (deg > 0.0f) ? rsqrtf(fmaxf(deg, 1e-38f)) : 0.0f;
            }
        }
    }
}

// ===========================================================================
// Fused: 256 thr, 2 blocks/SM, one window per block
// ===========================================================================
#define XH_O   0
#define XL_O   34816
#define SGH_O  69632
#define SGL_O  88064
#define DIS_O  106496
#define B1_O   107008
#define B2_O   107520
#define GM_O   108032
#define BT_O   108544
#define PSS_O  109056
#define PSQ_O  110080
#define FUSED_SMEM 111104

#define LDX 136
#define LDC 72

// one k16 step, warp tile 32x64; products swept hh->hl->lh per ng (RAW dist 4)
__device__ __forceinline__ void mma_k16(uint32_t sb,
        uint32_t aH, uint32_t aL, int lda, int ka0,
        uint32_t bH, uint32_t bL, int ldb, int kb0,
        float (*acc)[4], int lane, int wr, int wc){
    const int arow = lane & 15, chalf = (lane >> 4) << 3;
    uint32_t Ah[2][4], Al[2][4];
#pragma unroll
    for (int mi = 0; mi < 2; mi++){
        uint32_t off = (uint32_t)((wr*32 + mi*16 + arow) * lda + ka0 + chalf) * 2;
        ldsm4(sb + aH + off, Ah[mi]);
        ldsm4(sb + aL + off, Al[mi]);
    }
#pragma unroll
    for (int ng = 0; ng < 4; ng++){
        uint32_t off = (uint32_t)((wc*64 + ng*16 + arow) * ldb + kb0 + chalf) * 2;
        uint32_t Bh[4], Bl[4];
        ldsm4(sb + bH + off, Bh);
        ldsm4(sb + bL + off, Bl);
        // hh sweep
#pragma unroll
        for (int mi = 0; mi < 2; mi++){
            mma16816(acc[mi*8 + ng*2],     Ah[mi], Bh[0], Bh[2]);
            mma16816(acc[mi*8 + ng*2 + 1], Ah[mi], Bh[1], Bh[3]);
        }
        // hl sweep
#pragma unroll
        for (int mi = 0; mi < 2; mi++){
            mma16816(acc[mi*8 + ng*2],     Ah[mi], Bl[0], Bl[2]);
            mma16816(acc[mi*8 + ng*2 + 1], Ah[mi], Bl[1], Bl[3]);
        }
        // lh sweep
#pragma unroll
        for (int mi = 0; mi < 2; mi++){
            mma16816(acc[mi*8 + ng*2],     Al[mi], Bh[0], Bh[2]);
            mma16816(acc[mi*8 + ng*2 + 1], Al[mi], Bh[1], Bh[3]);
        }
    }
}

__device__ __forceinline__ void stage_chunk(uint32_t sb,
        const unsigned short* __restrict__ sh, const unsigned short* __restrict__ sl,
        int kc, int tid){
    const char* gh = (const char*)sh + kc*128;
    const char* gl = (const char*)sl + kc*128;
    for (int i = tid; i < 2048; i += 256){
        int half = i >> 10, j = i & 1023, r = j >> 3, s = j & 7;
        uint32_t dst = sb + (half ? SGL_O : SGH_O) + (uint32_t)r*(LDC*2) + s*16;
        const char* src = (half ? gl : gh) + (size_t)r*256 + s*16;
        asm volatile("cp.async.ca.shared.global [%0], [%1], 16;" :: "r"(dst), "l"(src));
    }
}

template<int MODE>
__device__ __forceinline__ void store_acc(uint8_t* smb, float (*acc)[4],
        const float* smf, int xo, int lane, int wr, int wc){
    const int g = lane >> 2, t = lane & 3;
#pragma unroll
    for (int mi = 0; mi < 2; mi++){
        int r0 = wr*32 + mi*16 + g;
#pragma unroll
        for (int ni = 0; ni < 8; ni++){
            int col = wc*64 + ni*8 + t*2;
            float* a = acc[mi*8 + ni];
            float v0 = a[0], v1 = a[1], v2 = a[2], v3 = a[3];
            if (MODE == 1){
                float s0 = smf[xo + r0], s1 = smf[xo + r0 + 8];
                v0 *= s0; v1 *= s0; v2 *= s1; v3 *= s1;
            }
            if (MODE == 2){
                float q0 = smf[xo + col], q1 = smf[xo + col + 1];
                v0 = fmaxf(v0 + q0, 0.0f); v1 = fmaxf(v1 + q1, 0.0f);
                v2 = fmaxf(v2 + q0, 0.0f); v3 = fmaxf(v3 + q1, 0.0f);
            }
            uint32_t h0,l0,h1,l1;
            split2(v0, v1, h0, l0);
            split2(v2, v3, h1, l1);
            uint32_t o0 = (uint32_t)(r0*LDX + col)*2, o1 = (uint32_t)((r0+8)*LDX + col)*2;
            *(uint32_t*)(smb + XH_O + o0) = h0;  *(uint32_t*)(smb + XL_O + o0) = l0;
            *(uint32_t*)(smb + XH_O + o1) = h1;  *(uint32_t*)(smb + XL_O + o1) = l1;
        }
    }
}

__device__ __forceinline__ void zero_acc(float (*acc)[4]){
#pragma unroll
    for (int i = 0; i < 16; i++)
#pragma unroll
        for (int j = 0; j < 4; j++) acc[i][j] = 0.0f;
}

__global__ __launch_bounds__(256, 2)
void fused_kernel(const float* __restrict__ feat,
                  const float* __restrict__ b1, const float* __restrict__ b2,
                  const float* __restrict__ gamma, const float* __restrict__ beta,
                  float* __restrict__ out){
    extern __shared__ uint8_t smb[];
    float* smf = (float*)smb;
    const uint32_t sb = smem_u32(smb);
    const int tid = threadIdx.x, wid = tid >> 5, lane = tid & 31;
    const int wr = wid & 3, wc = wid >> 2;

    const int bw = blockIdx.x;
    const int b = bw / TWw, tw = bw % TWw;
    const size_t bt0 = (size_t)(b*Tt + tw);

    stage_chunk(sb, g_fTh + bt0*TILE, g_fTl + bt0*TILE, 0, tid);
    CP_COMMIT();

    if (tid < 128){
        smf[B1_O/4 + tid] = b1[tid];
        smf[B2_O/4 + tid] = b2[tid];
        smf[GM_O/4 + tid] = gamma[tid];
        smf[BT_O/4 + tid] = beta[tid];
        smf[DIS_O/4 + tid] = g_DIS[(bt0 + 2)*384 + 256 + tid];
    }

    float acc[16][4];

    // ---- Stage C
    zero_acc(acc);
    for (int t2 = 0; t2 < 3; t2++){
        const size_t btt = bt0 + t2;
        if (t2){
            stage_chunk(sb, g_fTh + btt*TILE, g_fTl + btt*TILE, 0, tid);
            CP_COMMIT();
        }
        {   // B = dis-scaled wfT -> X (float4 loads, overlaps chunk0 cp.async)
            const float* wfTp = g_wfT + btt*TILE;
            const float4* disp4 = (const float4*)(g_DIS + (btt*3 + t2)*128);
            for (int i = tid; i < 4096; i += 256){
                int r = i >> 5, q = i & 31;
                int n0 = q*4;
                float4 v = *(const float4*)(wfTp + (size_t)r*128 + n0);
                float4 dd = disp4[q];
                uint32_t h0, l0, h1, l1;
                split2(v.x*dd.x, v.y*dd.y, h0, l0);
                split2(v.z*dd.z, v.w*dd.w, h1, l1);
                uint32_t o = (uint32_t)(r*LDX + n0)*2;
                *(uint2*)(smb + XH_O + o) = make_uint2(h0, h1);
                *(uint2*)(smb + XL_O + o) = make_uint2(l0, l1);
            }
        }
        CP_WAIT0();
        __syncthreads();
#pragma unroll
        for (int k = 0; k < 4; k++)
            mma_k16(sb, SGH_O, SGL_O, LDC, k*16, XH_O, XL_O, LDX, k*16, acc, lane, wr, wc);
        __syncthreads();
        stage_chunk(sb, g_fTh + btt*TILE, g_fTl + btt*TILE, 1, tid);
        CP_COMMIT(); CP_WAIT0();
        __syncthreads();
#pragma unroll
        for (int k = 0; k < 4; k++)
            mma_k16(sb, SGH_O, SGL_O, LDC, k*16, XH_O, XL_O, LDX, 64 + k*16, acc, lane, wr, wc);
        __syncthreads();
    }

    // ---- Stage D
    stage_chunk(sb, g_wfh + (bt0 + 2)*TILE, g_wfl + (bt0 + 2)*TILE, 0, tid);
    CP_COMMIT();
    store_acc<0>(smb, acc, smf, 0, lane, wr, wc);
    zero_acc(acc);
    CP_WAIT0();
    __syncthreads();
#pragma unroll
    for (int k = 0; k < 4; k++)
        mma_k16(sb, SGH_O, SGL_O, LDC, k*16, XH_O, XL_O, LDX, k*16, acc, lane, wr, wc);
    __syncthreads();
    stage_chunk(sb, g_wfh + (bt0 + 2)*TILE, g_wfl + (bt0 + 2)*TILE, 1, tid);
    CP_COMMIT(); CP_WAIT0();
    __syncthreads();
#pragma unroll
    for (int k = 0; k < 4; k++)
        mma_k16(sb, SGH_O, SGL_O, LDC, k*16, XH_O, XL_O, LDX, 64 + k*16, acc, lane, wr, wc);
    __syncthreads();

    // ---- Stage E
    stage_chunk(sb, g_W1h, g_W1l, 0, tid);
    CP_COMMIT();
    store_acc<1>(smb, acc, smf, DIS_O/4, lane, wr, wc);
    zero_acc(acc);
    CP_WAIT0();
    __syncthreads();
#pragma unroll
    for (int k = 0; k < 4; k++)
        mma_k16(sb, XH_O, XL_O, LDX, k*16, SGH_O, SGL_O, LDC, k*16, acc, lane, wr, wc);
    __syncthreads();
    stage_chunk(sb, g_W1h, g_W1l, 1, tid);
    CP_COMMIT(); CP_WAIT0();
    __syncthreads();
#pragma unroll
    for (int k = 0; k < 4; k++)
        mma_k16(sb, XH_O, XL_O, LDX, 64 + k*16, SGH_O, SGL_O, LDC, k*16, acc, lane, wr, wc);
    __syncthreads();

    // ---- Stage F
    stage_chunk(sb, g_W2h, g_W2l, 0, tid);
    CP_COMMIT();
    store_acc<2>(smb, acc, smf, B1_O/4, lane, wr, wc);
    zero_acc(acc);
    CP_WAIT0();
    __syncthreads();
#pragma unroll
    for (int k = 0; k < 4; k++)
        mma_k16(sb, XH_O, XL_O, LDX, k*16, SGH_O, SGL_O, LDC, k*16, acc, lane, wr, wc);
    __syncthreads();
    stage_chunk(sb, g_W2h, g_W2l, 1, tid);
    CP_COMMIT(); CP_WAIT0();
    __syncthreads();
#pragma unroll
    for (int k = 0; k < 4; k++)
        mma_k16(sb, XH_O, XL_O, LDX, 64 + k*16, SGH_O, SGL_O, LDC, k*16, acc, lane, wr, wc);

    // ---- Epilogue
    {
        const int g = lane >> 2, t = lane & 3;
        const float* featLast = feat + (bt0 + 2)*TILE;
#pragma unroll
        for (int mi = 0; mi < 2; mi++){
            int r0 = wr*32 + mi*16 + g;
            float s0 = 0.0f, q0 = 0.0f, s1 = 0.0f, q1 = 0.0f;
#pragma unroll
            for (int ni = 0; ni < 8; ni++){
                int col = wc*64 + ni*8 + t*2;
                float* a = acc[mi*8 + ni];
                float bb0 = smf[B2_O/4 + col], bb1 = smf[B2_O/4 + col + 1];
                float2 f0 = *(const float2*)(featLast + r0*128 + col);
                float2 f1 = *(const float2*)(featLast + (r0+8)*128 + col);
                a[0] += bb0 + f0.x; a[1] += bb1 + f0.y;
                a[2] += bb0 + f1.x; a[3] += bb1 + f1.y;
                s0 += a[0] + a[1];  q0 += a[0]*a[0] + a[1]*a[1];
                s1 += a[2] + a[3];  q1 += a[2]*a[2] + a[3]*a[3];
            }
            s0 += __shfl_xor_sync(0xffffffffu, s0, 1); s0 += __shfl_xor_sync(0xffffffffu, s0, 2);
            q0 += __shfl_xor_sync(0xffffffffu, q0, 1); q0 += __shfl_xor_sync(0xffffffffu, q0, 2);
            s1 += __shfl_xor_sync(0xffffffffu, s1, 1); s1 += __shfl_xor_sync(0xffffffffu, s1, 2);
            q1 += __shfl_xor_sync(0xffffffffu, q1, 1); q1 += __shfl_xor_sync(0xffffffffu, q1, 2);
            if (t == 0){
                smf[PSS_O/4 + r0*2 + wc] = s0;       smf[PSQ_O/4 + r0*2 + wc] = q0;
                smf[PSS_O/4 + (r0+8)*2 + wc] = s1;   smf[PSQ_O/4 + (r0+8)*2 + wc] = q1;
            }
        }
        __syncthreads();
        float* outp = out + (size_t)(b*TWw + tw)*TILE;
#pragma unroll
        for (int mi = 0; mi < 2; mi++){
            int r0 = wr*32 + mi*16 + g;
            float S0 = smf[PSS_O/4 + r0*2] + smf[PSS_O/4 + r0*2 + 1];
            float Q0 = smf[PSQ_O/4 + r0*2] + smf[PSQ_O/4 + r0*2 + 1];
            float S1 = smf[PSS_O/4 + (r0+8)*2] + smf[PSS_O/4 + (r0+8)*2 + 1];
            float Q1 = smf[PSQ_O/4 + (r0+8)*2] + smf[PSQ_O/4 + (r0+8)*2 + 1];
            float mu0 = S0 * 0.0078125f, mu1 = S1 * 0.0078125f;
            float rs0 = rsqrtf(Q0*0.0078125f - mu0*mu0 + 1e-5f);
            float rs1 = rsqrtf(Q1*0.0078125f - mu1*mu1 + 1e-5f);
#pragma unroll
            for (int ni = 0; ni < 8; ni++){
                int col = wc*64 + ni*8 + t*2;
                float* a = acc[mi*8 + ni];
                float gm0 = smf[GM_O/4 + col], gm1 = smf[GM_O/4 + col + 1];
                float bt0v = smf[BT_O/4 + col], bt1v = smf[BT_O/4 + col + 1];
                float2 o0, o1;
                o0.x = (a[0] - mu0)*rs0*gm0 + bt0v;
                o0.y = (a[1] - mu0)*rs0*gm1 + bt1v;
                o1.x = (a[2] - mu1)*rs1*gm0 + bt0v;
                o1.y = (a[3] - mu1)*rs1*gm1 + bt1v;
                *(float2*)(outp + r0*128 + col)     = o0;
                *(float2*)(outp + (r0+8)*128 + col) = o1;
            }
        }
    }
}

// ---------------------------------------------------------------------------
extern "C" void kernel_launch(void* const* d_in, const int* in_sizes, int n_in,
                              void* d_out, int out_size) {
    const float* feat  = (const float*)d_in[0];
    const float* w     = (const float*)d_in[1];
    const float* W1    = (const float*)d_in[2];
    const float* b1    = (const float*)d_in[3];
    const float* W2    = (const float*)d_in[4];
    const float* b2    = (const float*)d_in[5];
    const float* gamma = (const float*)d_in[6];
    const float* beta  = (const float*)d_in[7];
    float* out = (float*)d_out;

    cudaFuncSetAttribute(fused_kernel, cudaFuncAttributeMaxDynamicSharedMemorySize,
                         FUSED_SMEM);

    prep_kernel<<<NBT, 256>>>(feat, w);
    deg_kernel<<<NBT + 8, 256>>>(W1, W2);
    fused_kernel<<<NWIN, 256, FUSED_SMEM>>>(feat, b1, b2, gamma, beta, out);
}